// round 1
// baseline (speedup 1.0000x reference)
#include <cuda_runtime.h>
#include <cuda_bf16.h>
#include <math.h>

// Problem constants
#define BB 4
#define SS 8192
#define EE 1024
#define HH 16
#define DD 64
#define LL 64

#define MROWS (BB * SS)            // 32768
#define MSZ   ((size_t)MROWS * EE) // 33554432 elements

// ---------------- scratch (device globals; no allocations allowed) ----------
__device__ float g_Q[MSZ];
__device__ float g_K[MSZ];
__device__ float g_V[MSZ];
__device__ float g_ctx[MSZ];
__device__ float g_scores[BB * SS];
__device__ int   g_idx[BB * LL];
__device__ float g_Ksp[BB * HH * LL * DD];
__device__ float g_Vsp[BB * HH * LL * DD];

// ---------------- SGEMM: C[M,1024] = A[M,1024] @ W[1024,1024]^T + bias ------
// BM=128, BN=128, BK=16, 256 threads, 8x8 microtile per thread.
__global__ __launch_bounds__(256) void sgemm_bias(
    const float* __restrict__ A, const float* __restrict__ W,
    const float* __restrict__ bias, float* __restrict__ C, int M)
{
    const int K = 1024, N = 1024;
    __shared__ float As[16][128];
    __shared__ float Ws[16][128];

    const int bm = blockIdx.y * 128;
    const int bn = blockIdx.x * 128;
    const int tid = threadIdx.x;
    const int tx = tid & 15, ty = tid >> 4;
    const int row0 = ty * 8, col0 = tx * 8;

    // load mapping: each thread loads 2 float4 of A and 2 float4 of W per k-tile
    const int lr = tid >> 2;            // 0..63
    const int lk = (tid & 3) * 4;       // 0,4,8,12
    const float* Ap = A + (size_t)(bm + lr) * K + lk;
    const float* Wp = W + (size_t)(bn + lr) * K + lk;

    float acc[8][8];
    #pragma unroll
    for (int i = 0; i < 8; i++)
        #pragma unroll
        for (int j = 0; j < 8; j++) acc[i][j] = 0.f;

    for (int kt = 0; kt < K; kt += 16) {
        float4 a0 = *(const float4*)(Ap + kt);
        float4 a1 = *(const float4*)(Ap + kt + (size_t)64 * K);
        float4 w0 = *(const float4*)(Wp + kt);
        float4 w1 = *(const float4*)(Wp + kt + (size_t)64 * K);

        __syncthreads();   // previous tile fully consumed before overwrite
        As[lk + 0][lr] = a0.x; As[lk + 1][lr] = a0.y;
        As[lk + 2][lr] = a0.z; As[lk + 3][lr] = a0.w;
        As[lk + 0][lr + 64] = a1.x; As[lk + 1][lr + 64] = a1.y;
        As[lk + 2][lr + 64] = a1.z; As[lk + 3][lr + 64] = a1.w;
        Ws[lk + 0][lr] = w0.x; Ws[lk + 1][lr] = w0.y;
        Ws[lk + 2][lr] = w0.z; Ws[lk + 3][lr] = w0.w;
        Ws[lk + 0][lr + 64] = w1.x; Ws[lk + 1][lr + 64] = w1.y;
        Ws[lk + 2][lr + 64] = w1.z; Ws[lk + 3][lr + 64] = w1.w;
        __syncthreads();

        #pragma unroll
        for (int kk = 0; kk < 16; kk++) {
            float ar[8], br[8];
            #pragma unroll
            for (int i = 0; i < 8; i++) ar[i] = As[kk][row0 + i];
            #pragma unroll
            for (int j = 0; j < 8; j++) br[j] = Ws[kk][col0 + j];
            #pragma unroll
            for (int i = 0; i < 8; i++)
                #pragma unroll
                for (int j = 0; j < 8; j++)
                    acc[i][j] = fmaf(ar[i], br[j], acc[i][j]);
        }
    }

    float bsv[8];
    #pragma unroll
    for (int j = 0; j < 8; j++) bsv[j] = bias[bn + col0 + j];

    #pragma unroll
    for (int i = 0; i < 8; i++) {
        float* cp = C + (size_t)(bm + row0 + i) * N + bn + col0;
        float4 o0, o1;
        o0.x = acc[i][0] + bsv[0]; o0.y = acc[i][1] + bsv[1];
        o0.z = acc[i][2] + bsv[2]; o0.w = acc[i][3] + bsv[3];
        o1.x = acc[i][4] + bsv[4]; o1.y = acc[i][5] + bsv[5];
        o1.z = acc[i][6] + bsv[6]; o1.w = acc[i][7] + bsv[7];
        *(float4*)(cp)     = o0;
        *(float4*)(cp + 4) = o1;
    }
}

// ---------------- scores[b,s] = mean_h ||K[b,s,h*64:+64]||_2 ---------------
__global__ __launch_bounds__(256) void scores_kernel(
    const float* __restrict__ Km, float* __restrict__ scores)
{
    int row  = blockIdx.x * 8 + (threadIdx.x >> 5);   // b*S+s
    int lane = threadIdx.x & 31;
    const float* kr = Km + (size_t)row * EE;
    float acc = 0.f;
    #pragma unroll
    for (int h = 0; h < HH; h++) {
        float x0 = kr[h * 64 + lane];
        float x1 = kr[h * 64 + 32 + lane];
        float ss = x0 * x0 + x1 * x1;
        #pragma unroll
        for (int o = 16; o > 0; o >>= 1)
            ss += __shfl_xor_sync(0xffffffffu, ss, o);
        acc += sqrtf(ss);
    }
    if (lane == 0) scores[row] = acc * (1.f / 16.f);
}

// ---------------- exact top-64 per batch (desc value, tie -> lower idx) ----
__global__ __launch_bounds__(256) void topk_kernel(
    const float* __restrict__ scores, int* __restrict__ idxout)
{
    __shared__ float sv[SS];
    __shared__ float rv[256];
    __shared__ int   ri[256];
    const int b = blockIdx.x, t = threadIdx.x;
    for (int i = t; i < SS; i += 256) sv[i] = scores[b * SS + i];
    __syncthreads();

    for (int l = 0; l < LL; l++) {
        float m = -INFINITY; int a = 0;
        for (int i = t; i < SS; i += 256) {
            float v = sv[i];
            if (v > m) { m = v; a = i; }   // ascending scan keeps lowest idx on tie
        }
        rv[t] = m; ri[t] = a;
        __syncthreads();
        for (int s = 128; s > 0; s >>= 1) {
            if (t < s) {
                float v2 = rv[t + s]; int a2 = ri[t + s];
                if (v2 > rv[t] || (v2 == rv[t] && a2 < ri[t])) { rv[t] = v2; ri[t] = a2; }
            }
            __syncthreads();
        }
        if (t == 0) { idxout[b * LL + l] = ri[0]; sv[ri[0]] = -INFINITY; }
        __syncthreads();
    }
}

// ---------------- gather K_sp/V_sp [B,H,L,D] --------------------------------
__global__ __launch_bounds__(256) void gather_kernel(
    const float* __restrict__ Km, const float* __restrict__ Vm,
    const int* __restrict__ idx,
    float* __restrict__ Ksp, float* __restrict__ Vsp)
{
    int i = blockIdx.x * 256 + threadIdx.x;   // over B*H*L*D = 262144
    int d = i & 63;
    int l = (i >> 6) & 63;
    int h = (i >> 12) & 15;
    int b = i >> 16;
    int s = idx[b * LL + l];
    size_t src = ((size_t)(b * SS + s)) * EE + h * 64 + d;
    Ksp[i] = Km[src];
    Vsp[i] = Vm[src];
}

// ---------------- attention: scores, softmax (-> w out), ctx ---------------
// Block: 64 threads, one (b, h, 64-row s-chunk). smem = exactly 48KB static.
__global__ __launch_bounds__(64) void attn_kernel(
    const float* __restrict__ Q, const float* __restrict__ Ksp,
    const float* __restrict__ Vsp, float* __restrict__ w_out,
    float* __restrict__ ctx)
{
    __shared__ float Kt[64 * 64];
    __shared__ float Vt[64 * 64];
    __shared__ float sc[64 * 64];   // sc[l*64 + thread] : conflict-free

    const int b = blockIdx.z, h = blockIdx.y, chunk = blockIdx.x;
    const int i = threadIdx.x;

    const float* Kg = Ksp + ((size_t)(b * HH + h) << 12);
    const float* Vg = Vsp + ((size_t)(b * HH + h) << 12);
    for (int j = i; j < 1024; j += 64) {         // 1024 float4 per tile
        ((float4*)Kt)[j] = ((const float4*)Kg)[j];
        ((float4*)Vt)[j] = ((const float4*)Vg)[j];
    }
    __syncthreads();

    const int s = chunk * 64 + i;
    const float* qp = Q + ((size_t)(b * SS + s)) * EE + h * 64;
    float4 q4[16];
    #pragma unroll
    for (int j = 0; j < 16; j++) q4[j] = ((const float4*)qp)[j];

    float mx = -INFINITY;
    #pragma unroll 4
    for (int l = 0; l < 64; l++) {
        const float4* kl = (const float4*)(Kt + l * 64);
        float acc = 0.f;
        #pragma unroll
        for (int j = 0; j < 16; j++) {
            float4 kv = kl[j];
            acc = fmaf(q4[j].x, kv.x, acc);
            acc = fmaf(q4[j].y, kv.y, acc);
            acc = fmaf(q4[j].z, kv.z, acc);
            acc = fmaf(q4[j].w, kv.w, acc);
        }
        acc *= 0.125f;                // 1/sqrt(D)
        sc[l * 64 + i] = acc;
        mx = fmaxf(mx, acc);
    }

    float sum = 0.f;
    #pragma unroll 4
    for (int l = 0; l < 64; l++) {
        float e = expf(sc[l * 64 + i] - mx);
        sc[l * 64 + i] = e;
        sum += e;
    }
    const float inv = 1.f / sum;

    float4 c4[16];
    #pragma unroll
    for (int j = 0; j < 16; j++) c4[j] = make_float4(0.f, 0.f, 0.f, 0.f);

    float* wp = w_out + ((size_t)((b * HH + h) * SS + s)) * LL;
    #pragma unroll 2
    for (int l = 0; l < 64; l++) {
        float wl = sc[l * 64 + i] * inv;
        wp[l] = wl;
        const float4* vl = (const float4*)(Vt + l * 64);
        #pragma unroll
        for (int j = 0; j < 16; j++) {
            float4 vv = vl[j];
            c4[j].x = fmaf(wl, vv.x, c4[j].x);
            c4[j].y = fmaf(wl, vv.y, c4[j].y);
            c4[j].z = fmaf(wl, vv.z, c4[j].z);
            c4[j].w = fmaf(wl, vv.w, c4[j].w);
        }
    }

    float* cp = ctx + ((size_t)(b * SS + s)) * EE + h * 64;
    #pragma unroll
    for (int j = 0; j < 16; j++) ((float4*)cp)[j] = c4[j];
}

// ---------------- launch ----------------------------------------------------
extern "C" void kernel_launch(void* const* d_in, const int* in_sizes, int n_in,
                              void* d_out, int out_size)
{
    const float* query = (const float*)d_in[0];
    const float* key   = (const float*)d_in[1];
    const float* value = (const float*)d_in[2];
    const float* Wq = (const float*)d_in[3];
    const float* bq = (const float*)d_in[4];
    const float* Wk = (const float*)d_in[5];
    const float* bk = (const float*)d_in[6];
    const float* Wv = (const float*)d_in[7];
    const float* bv = (const float*)d_in[8];
    const float* Wo = (const float*)d_in[9];
    const float* bo = (const float*)d_in[10];

    float* out = (float*)d_out;                 // [B,S,E] -> first 33554432 floats
    float* wout = out + MSZ;                    // [B,H,S,L] -> next 33554432 floats

    float *pQ, *pK, *pV, *pC, *pScores, *pKsp, *pVsp;
    int* pIdx;
    cudaGetSymbolAddress((void**)&pQ, g_Q);
    cudaGetSymbolAddress((void**)&pK, g_K);
    cudaGetSymbolAddress((void**)&pV, g_V);
    cudaGetSymbolAddress((void**)&pC, g_ctx);
    cudaGetSymbolAddress((void**)&pScores, g_scores);
    cudaGetSymbolAddress((void**)&pIdx, g_idx);
    cudaGetSymbolAddress((void**)&pKsp, g_Ksp);
    cudaGetSymbolAddress((void**)&pVsp, g_Vsp);

    dim3 ggrid(EE / 128, MROWS / 128);          // (8, 256)

    sgemm_bias<<<ggrid, 256>>>(query, Wq, bq, pQ, MROWS);
    sgemm_bias<<<ggrid, 256>>>(key,   Wk, bk, pK, MROWS);
    sgemm_bias<<<ggrid, 256>>>(value, Wv, bv, pV, MROWS);

    scores_kernel<<<MROWS / 8, 256>>>(pK, pScores);
    topk_kernel<<<BB, 256>>>(pScores, pIdx);
    gather_kernel<<<(BB * HH * LL * DD) / 256, 256>>>(pK, pV, pIdx, pKsp, pVsp);

    dim3 agrid(SS / 64, HH, BB);                // (128, 16, 4)
    attn_kernel<<<agrid, 64>>>(pQ, pKsp, pVsp, wout, pC);

    sgemm_bias<<<ggrid, 256>>>(pC, Wo, bo, out, MROWS);
}